// round 15
// baseline (speedup 1.0000x reference)
#include <cuda_runtime.h>
#include <cuda_fp16.h>
#include <math.h>
#include <stdint.h>

#define BB 8
#define LL 2048
#define DM 512
#define DI 1024
#define NH 16
#define HD 64
#define CD 1056
#define DIP 2096
#define MT (BB*LL)      // 16384 tokens
#define CL 128          // scan chunk length
#define NC (LL/CL)      // 16 chunks
#define NSCAN 256       // 2 dirs * 8 batch * 16 heads

// ---------------- scratch (static device globals; no allocation) ----------------
__device__ __half g_zxh[2ull*MT*DIP];       // in_proj output in fp16
__device__ float  g_xbc[2ull*MT*CD];        // only BC region [DI, DI+32) used
__device__ float  g_dt [2ull*MT*NH];
__device__ float  g_dA [2ull*MT*NH];
__device__ float  g_y  [2ull*MT*DI];
__device__ float  g_P  [(size_t)NSCAN*LL];
__device__ float  g_S  [(size_t)NSCAN*NC*HD*16];
__device__ float  g_hin[(size_t)NSCAN*NC*HD*16];
__device__ __half g_xh [(size_t)MT*DM];
__device__ __half g_wih[2ull*DIP*DM];
__device__ __half g_woh[2ull*DM*DI];
__device__ __half g_gh [2ull*MT*DI];

__device__ __forceinline__ float siluf(float v)     { return v / (1.f + expf(-v)); }
__device__ __forceinline__ float softplusf(float v) { return fmaxf(v, 0.f) + log1pf(expf(-fabsf(v))); }
__device__ __forceinline__ void mma16(float* c, const uint32_t* a, const uint32_t* b) {
    asm volatile(
        "mma.sync.aligned.m16n8k16.row.col.f32.f16.f16.f32 "
        "{%0,%1,%2,%3}, {%4,%5,%6,%7}, {%8,%9}, {%0,%1,%2,%3};"
        : "+f"(c[0]), "+f"(c[1]), "+f"(c[2]), "+f"(c[3])
        : "r"(a[0]), "r"(a[1]), "r"(a[2]), "r"(a[3]), "r"(b[0]), "r"(b[1]));
}
__device__ __forceinline__ void ldsm4(uint32_t* r, uint32_t addr) {
    asm volatile("ldmatrix.sync.aligned.m8n8.x4.shared.b16 {%0,%1,%2,%3}, [%4];"
        : "=r"(r[0]), "=r"(r[1]), "=r"(r[2]), "=r"(r[3]) : "r"(addr));
}
__device__ __forceinline__ uint32_t s2u32(const void* p) {
    return (uint32_t)__cvta_generic_to_shared(p);
}
__device__ __forceinline__ void cpa16(const void* sp, const void* g) {
    asm volatile("cp.async.cg.shared.global [%0], [%1], 16;" :: "r"(s2u32(sp)), "l"(g));
}
__device__ __forceinline__ void cpa16p(const void* sp, const void* g, bool pred) {
    int sz = pred ? 16 : 0;
    asm volatile("cp.async.cg.shared.global [%0], [%1], 16, %2;" :: "r"(s2u32(sp)), "l"(g), "r"(sz));
}
__device__ __forceinline__ void cpa4(const void* sp, const void* g) {
    asm volatile("cp.async.ca.shared.global [%0], [%1], 4;" :: "r"(s2u32(sp)), "l"(g));
}
#define CP_COMMIT() asm volatile("cp.async.commit_group;" ::: "memory")
#define CP_WAIT(n)  asm volatile("cp.async.wait_group %0;" :: "n"(n) : "memory")

// ---------------- fp32 -> fp16 conversion prep (single launch, 5 regions) ----------------
#define N4_X  (MT*DM/4)
#define N4_WI (DIP*DM/4)
#define N4_WO (DM*DI/4)
__global__ __launch_bounds__(256)
void tohalf_all(const float4* __restrict__ x,
                const float4* __restrict__ wF, const float4* __restrict__ wB,
                const float4* __restrict__ oF, const float4* __restrict__ oB,
                __half2* __restrict__ xh, __half2* __restrict__ wih,
                __half2* __restrict__ woh)
{
    int i = blockIdx.x * 256 + threadIdx.x;
    const float4* s; __half2* d; int li;
    if (i < N4_X)                    { s = x;  d = xh;                li = i; }
    else if (i < N4_X + N4_WI)       { s = wF; d = wih;               li = i - N4_X; }
    else if (i < N4_X + 2*N4_WI)     { s = wB; d = wih + N4_WI*2;     li = i - N4_X - N4_WI; }
    else if (i < N4_X + 2*N4_WI + N4_WO) { s = oF; d = woh;           li = i - N4_X - 2*N4_WI; }
    else if (i < N4_X + 2*N4_WI + 2*N4_WO) { s = oB; d = woh + N4_WO*2; li = i - N4_X - 2*N4_WI - N4_WO; }
    else return;
    float4 v = s[li];
    d[2*li]   = __floats2half2_rn(v.x, v.y);
    d[2*li+1] = __floats2half2_rn(v.z, v.w);
}

// ============================================================================
// fp16 GEMM (BM=128, BN=128, BK=32; 8 warps 2x4, warp tile 64x32), 3-stage,
// ldmatrix fragment loads. smem row stride 40 halfs (80B), conflict-free.
// ============================================================================
#define GEMM_SMEM 61440
#define ASMD(st,r,kh) ((void*)(sAh + (((st)*128 + (r))*40 + (kh))))
#define BSMD(st,r,kh) ((void*)(sBh + (((st)*128 + (r))*40 + (kh))))

#define GEMM_PROLOGUE \
    extern __shared__ __align__(16) char smraw[]; \
    __half* sAh = (__half*)smraw; \
    __half* sBh = (__half*)(smraw + 3*128*80); \
    const uint32_t sA32 = s2u32(sAh); \
    const uint32_t sB32 = s2u32(sBh); \
    const int tid  = threadIdx.x; \
    const int lane = tid & 31; \
    const int wid  = tid >> 5; \
    const int mw   = wid & 1; \
    const int nw   = wid >> 1; \
    const int g = lane >> 2; \
    const int q = lane & 3; \
    const int r8  = lane & 7; \
    const int sub = lane >> 3; \
    float acc[4][4][4]; \
    _Pragma("unroll") for (int i = 0; i < 4; i++) \
    _Pragma("unroll") for (int j = 0; j < 4; j++) \
    _Pragma("unroll") for (int r = 0; r < 4; r++) acc[i][j][r] = 0.f;

#define GEMM_COMPUTE(cur) \
    { \
      const uint32_t abase = sA32 + (uint32_t)((((cur)*128 + mw*64 + (sub&1)*8 + r8)*40 + (sub>>1)*8)*2); \
      const uint32_t bbase = sB32 + (uint32_t)((((cur)*128 + nw*32 + (sub>>1)*8 + r8)*40 + (sub&1)*8)*2); \
      _Pragma("unroll") \
      for (int kk = 0; kk < 32; kk += 16) { \
        uint32_t af[4][4], bp0[4], bp1[4]; \
        _Pragma("unroll") \
        for (int mt = 0; mt < 4; mt++) ldsm4(af[mt], abase + mt*(16*80) + kk*2); \
        ldsm4(bp0, bbase + kk*2); \
        ldsm4(bp1, bbase + 16*80 + kk*2); \
        _Pragma("unroll") \
        for (int mt = 0; mt < 4; mt++) { \
            mma16(acc[mt][0], af[mt], bp0); \
            mma16(acc[mt][1], af[mt], bp0 + 2); \
            mma16(acc[mt][2], af[mt], bp1); \
            mma16(acc[mt][3], af[mt], bp1 + 2); \
        } \
      } \
    }

#define GEMM_MAINLOOP(T) \
    load_tile(0, 0); CP_COMMIT(); \
    load_tile(1, 1); CP_COMMIT(); \
    load_tile(2, 2); CP_COMMIT(); \
    for (int kt = 0; kt < (T); kt++) { \
        const int cur = kt % 3; \
        if (kt + 2 < (T)) { CP_WAIT(2); } \
        else if (kt + 1 < (T)) { CP_WAIT(1); } \
        else { CP_WAIT(0); } \
        __syncthreads(); \
        GEMM_COMPUTE(cur) \
        __syncthreads(); \
        if (kt + 3 < (T)) { load_tile(kt + 3, cur); CP_COMMIT(); } \
    }

// ---------------- in_proj (+ fused dadt tail blocks): grid (18,128,2) ----------------
__global__ void __launch_bounds__(256, 2)
gemm_in(const __half* __restrict__ Ah, const __half* __restrict__ Bh0,
        const __half* __restrict__ Bh1, __half* __restrict__ Cb,
        const float* __restrict__ x,
        const float* __restrict__ ipwF, const float* __restrict__ ipwB,
        const float* __restrict__ dbF,  const float* __restrict__ alF,
        const float* __restrict__ dbB,  const float* __restrict__ alB)
{
    if (blockIdx.x == 17) {
        extern __shared__ __align__(16) char smraw[];
        float (*sW)[512] = (float(*)[512])smraw;
        const int d  = blockIdx.z;
        const int tb = blockIdx.y;
        const int tid = threadIdx.x;
        const float* W = (d ? ipwB : ipwF) + (size_t)(DI + CD) * DM;
#pragma unroll
        for (int j = 0; j < 8; j++)
            ((float4*)&sW[0][0])[j * 256 + tid] = ((const float4*)W)[j * 256 + tid];
        __syncthreads();

        const int h = tid >> 4, l = tid & 15;
        const float db = (d ? dbB : dbF)[h];
        const float Av = -expf((d ? alB : alF)[h]);

        for (int tk = 0; tk < 128; tk++) {
            int token = tb * 128 + tk;
            const float4* xr = (const float4*)(x + (size_t)token * DM);
            const float4* wr = (const float4*)&sW[h][0];
            float s = 0.f;
#pragma unroll
            for (int j = 0; j < 8; j++) {
                float4 xv = xr[l + 16 * j];
                float4 wv = wr[l + 16 * j];
                s = fmaf(xv.x, wv.x, s); s = fmaf(xv.y, wv.y, s);
                s = fmaf(xv.z, wv.z, s); s = fmaf(xv.w, wv.w, s);
            }
            s += __shfl_xor_sync(~0u, s, 1);
            s += __shfl_xor_sync(~0u, s, 2);
            s += __shfl_xor_sync(~0u, s, 4);
            s += __shfl_xor_sync(~0u, s, 8);
            if (l == 0) {
                float dt = softplusf(s + db);
                size_t r = (size_t)d * MT + token;
                g_dt[r * NH + h] = dt;
                g_dA[r * NH + h] = expf(dt * Av);
            }
        }
        return;
    }

    const __half* B = blockIdx.z ? Bh1 : Bh0;
    __half* C = Cb + (size_t)blockIdx.z * MT * DIP;
    const int m0 = blockIdx.y * 128, n0 = blockIdx.x * 128;
    const int N = DIP, K = DM;

    GEMM_PROLOGUE

    auto load_tile = [&](int kt, int buf) {
        const int k0 = kt << 5;
#pragma unroll
        for (int i = 0; i < 2; i++) {
            int id  = tid + (i << 8);
            int row = id >> 2;
            int seg = (id & 3) << 3;
            cpa16(ASMD(buf, row, seg), Ah + (size_t)(m0 + row) * K + k0 + seg);
            cpa16p(BSMD(buf, row, seg), B + (size_t)(n0 + row) * K + k0 + seg,
                   (n0 + row) < N);
        }
    };

    GEMM_MAINLOOP(K >> 5)

#pragma unroll
    for (int mt = 0; mt < 4; mt++) {
        int row = m0 + mw * 64 + mt * 16 + g;
#pragma unroll
        for (int nt = 0; nt < 4; nt++) {
            int n = n0 + nw * 32 + nt * 8 + q * 2;
            if (n < N) {
                *(__half2*)(C + (size_t)row * DIP + n) =
                    __floats2half2_rn(acc[mt][nt][0], acc[mt][nt][1]);
                *(__half2*)(C + (size_t)(row + 8) * DIP + n) =
                    __floats2half2_rn(acc[mt][nt][2], acc[mt][nt][3]);
            }
        }
    }
}

// ---------------- out_proj: K-concat of fwd+bwd (K=2048) -> single write ----------------
__global__ void __launch_bounds__(256, 2)
gemm_out(const __half* __restrict__ A0, const __half* __restrict__ A1,
         const __half* __restrict__ B0, const __half* __restrict__ B1,
         float* __restrict__ C)
{
    const int m0 = blockIdx.y * 128, n0 = blockIdx.x * 128;
    const int K = 2 * DI;

    GEMM_PROLOGUE

    auto load_tile = [&](int kt, int buf) {
        const int k0 = kt << 5;
        const __half* Ap; const __half* Bp; int kl;
        if (k0 < DI) { Ap = A0; Bp = B0; kl = k0; }
        else         { Ap = A1; Bp = B1; kl = k0 - DI; }
#pragma unroll
        for (int i = 0; i < 2; i++) {
            int id  = tid + (i << 8);
            int row = id >> 2;
            int seg = (id & 3) << 3;
            cpa16(ASMD(buf, row, seg), Ap + (size_t)(m0 + row) * DI + kl + seg);
            cpa16(BSMD(buf, row, seg), Bp + (size_t)(n0 + row) * DI + kl + seg);
        }
    };

    GEMM_MAINLOOP(K >> 5)

#pragma unroll
    for (int mt = 0; mt < 4; mt++) {
        int row = m0 + mw * 64 + mt * 16 + g;
#pragma unroll
        for (int nt = 0; nt < 4; nt++) {
            int n = n0 + nw * 32 + nt * 8 + q * 2;
            *(float2*)(C + (size_t)row * DM + n) =
                make_float2(acc[mt][nt][0], acc[mt][nt][1]);
            *(float2*)(C + (size_t)(row + 8) * DM + n) =
                make_float2(acc[mt][nt][2], acc[mt][nt][3]);
        }
    }
}

// ---------------- depthwise conv(4) + bias + SiLU — B/C channels only ----------------
#define CTT 16
__global__ __launch_bounds__(256)
void conv_bc_k(const float* __restrict__ cwF, const float* __restrict__ cbF,
               const float* __restrict__ cwB, const float* __restrict__ cbB)
{
    int idx = blockIdx.x * 256 + threadIdx.x;
    int  c  = DI + (idx & 31);
    int  q2 = idx >> 5;
    int  tg = q2 & (LL / CTT - 1);
    int  bd = q2 >> 7;
    int  b  = bd & 7, d = bd >> 3;
    int  t0 = tg * CTT;

    const float* wv = (d == 0 ? cwF : cwB) + c * 4;
    float w0 = wv[0], w1 = wv[1], w2 = wv[2], w3 = wv[3];
    float bias = (d == 0 ? cbF : cbB)[c];
    long rbase = (long)d * MT + (long)b * LL;
    const __half* zin = g_zxh + rbase * (long)DIP + DI + c;
    float* outp = g_xbc + (rbase + t0) * (long)CD + c;

    float in[CTT + 3];
    if (d == 0) {
#pragma unroll
        for (int j = 0; j < CTT + 3; j++) {
            int tt = t0 - 3 + j;
            in[j] = (tt >= 0) ? __half2float(zin[(long)tt * DIP]) : 0.f;
        }
#pragma unroll
        for (int i = 0; i < CTT; i++) {
            float a = bias;
            a = fmaf(w0, in[i], a); a = fmaf(w1, in[i+1], a);
            a = fmaf(w2, in[i+2], a); a = fmaf(w3, in[i+3], a);
            outp[(long)i * CD] = siluf(a);
        }
    } else {
#pragma unroll
        for (int j = 0; j < CTT + 3; j++) {
            int tt = t0 + j;
            in[j] = (tt < LL) ? __half2float(zin[(long)tt * DIP]) : 0.f;
        }
#pragma unroll
        for (int i = 0; i < CTT; i++) {
            float a = bias;
            a = fmaf(w3, in[i], a); a = fmaf(w2, in[i+1], a);
            a = fmaf(w1, in[i+2], a); a = fmaf(w0, in[i+3], a);
            outp[(long)i * CD] = siluf(a);
        }
    }
}

// ---------------- scan pass 1: 2 heads per block (128 thr), fused x-conv ----------------
__global__ __launch_bounds__(128)
void chunk_scan_k(const float* __restrict__ DpF, const float* __restrict__ DpB,
                  const float* __restrict__ cwF, const float* __restrict__ cbF,
                  const float* __restrict__ cwB, const float* __restrict__ cbB)
{
    int blk  = blockIdx.x;           // 2048 = 2d * 8b * 8hp * 16c
    int c    = blk & (NC - 1);
    int rest = blk >> 4;             // 128
    int hp   = rest & 7;
    int b    = (rest >> 3) & 7;
    int d    = rest >> 6;
    int tid  = threadIdx.x;
    int hl   = tid >> 6;             // 0/1: which head of the pair
    int p    = tid & 63;
    int h    = hp * 2 + hl;
    int sid  = d * 128 + b * 16 + h;

    __shared__ float  sBC[2][8][36];     // B16,C16 per step (shared by both heads)
    __shared__ __half sZ [2][2][11][64]; // z rows per head
    __shared__ float  sDT[2][8][2], sDA[2][8][2];

    float hs[16];
#pragma unroll
    for (int n = 0; n < 16; n++) hs[n] = 0.f;
    float dp = (d == 0 ? DpF : DpB)[h];
    long base0 = (long)d * MT + (long)b * LL;
    int s0 = c * CL;

    const int ch = h * HD + p;
    const float* wv = (d == 0 ? cwF : cwB) + ch * 4;
    const float w0 = wv[0], w1 = wv[1], w2 = wv[2], w3 = wv[3];
    const float cbias = (d == 0 ? cbF : cbB)[ch];

    auto rowof = [&](int s) -> long {
        int t = (d == 0) ? s : (LL - 1 - s);
        return base0 + t;
    };
    auto loadgrp = [&](int gg, int buf) {
        if (tid < 64) {   // B/C: 64 x 16B (shared across heads)
            int j = tid >> 3, seg = tid & 7;
            long row = rowof(s0 + gg * 8 + j);
            cpa16(&sBC[buf][j][seg * 4], &g_xbc[row * (long)CD + DI + seg * 4]);
        }
        // z rows: 2 heads x 88 segments = 176 x 16B
#pragma unroll
        for (int it = 0; it < 2; it++) {
            int idx2 = tid + it * 128;
            if (idx2 < 176) {
                int hl2 = idx2 / 88;
                int r   = idx2 - hl2 * 88;
                int j = r >> 3, seg = r & 7;
                int t = (d == 0) ? (s0 + gg * 8 - 3 + j)
                                 : (LL - 8 - s0 - gg * 8 + j);
                void* dst = (void*)&sZ[buf][hl2][j][seg * 8];
                if ((unsigned)t < (unsigned)LL)
                    cpa16(dst, &g_zxh[(base0 + t) * (long)DIP + DI
                                      + (hp * 2 + hl2) * HD + seg * 8]);
                else
                    *(uint4*)dst = make_uint4(0, 0, 0, 0);
            }
        }
        if (tid >= 96) {  // dt/dA: 2 heads x 8 rows x 2 vals = 32 x 4B
            int k = tid - 96;
            int hl2 = k >> 4, r = k & 15;
            int hh = hp * 2 + hl2;
            if (r < 8) {
                long row = rowof(s0 + gg * 8 + r);
                cpa4(&sDT[buf][r][hl2], &g_dt[row * (long)NH + hh]);
            } else {
                long row = rowof(s0 + gg * 8 + r - 8);
                cpa4(&sDA[buf][r - 8][hl2], &g_dA[row * (long)NH + hh]);
            }
        }
    };

    loadgrp(0, 0);
    CP_COMMIT();

    float P = 1.f;
    for (int gg = 0; gg < 16; gg++) {
        int buf = gg & 1;
        if (gg + 1 < 16) {
            loadgrp(gg + 1, buf ^ 1);
            CP_COMMIT();
            CP_WAIT(1);
        } else {
            CP_WAIT(0);
        }
        __syncthreads();
#pragma unroll
        for (int j = 0; j < 8; j++) {
            // fused depthwise conv + SiLU
            float a = cbias;
            if (d == 0) {
                a = fmaf(w0, __half2float(sZ[buf][hl][j    ][p]), a);
                a = fmaf(w1, __half2float(sZ[buf][hl][j + 1][p]), a);
                a = fmaf(w2, __half2float(sZ[buf][hl][j + 2][p]), a);
                a = fmaf(w3, __half2float(sZ[buf][hl][j + 3][p]), a);
            } else {
                a = fmaf(w3, __half2float(sZ[buf][hl][7 - j ][p]), a);
                a = fmaf(w2, __half2float(sZ[buf][hl][8 - j ][p]), a);
                a = fmaf(w1, __half2float(sZ[buf][hl][9 - j ][p]), a);
                a = fmaf(w0, __half2float(sZ[buf][hl][10 - j][p]), a);
            }
            float xv = siluf(a);

            float dtv = sDT[buf][j][hl], dAv = sDA[buf][j][hl];
            float coef = dtv * xv;
            float y = 0.f;
#pragma unroll
            for (int n = 0; n < 16; n += 2) {
                float2 Bn = *(const float2*)&sBC[buf][j][n];
                float2 Cn = *(const float2*)&sBC[buf][j][16 + n];
                hs[n]   = fmaf(hs[n],   dAv, coef * Bn.x);
                y       = fmaf(hs[n],   Cn.x, y);
                hs[n+1] = fmaf(hs[n+1], dAv, coef * Bn.y);
                y       = fmaf(hs[n+1], Cn.y, y);
            }
            P *= dAv;
            int s = s0 + gg * 8 + j;
            g_y[rowof(s) * (long)DI + h * HD + p] = fmaf(dp, xv, y);
            if (p == 0) g_P[(size_t)sid * LL + s] = P;
        }
        __syncthreads();
    }

    float* Sp = g_S + ((size_t)sid * NC + c) * (HD * 16) + p * 16;
#pragma unroll
    for (int n = 0; n < 16; n++) Sp[n] = hs[n];
}

// ---------------- scan pass 2: 2 scans per block, prefetched ----------------
__global__ __launch_bounds__(128)
void state_scan_k()
{
    int blk = blockIdx.x;            // 128
    int tid = threadIdx.x;
    int hl  = tid >> 6, p = tid & 63;
    int sid = blk * 2 + hl;

    __shared__ float sP[2][16];
    if (tid < 32) {
        int hl2 = tid >> 4, cc = tid & 15;
        sP[hl2][cc] = g_P[(size_t)(blk * 2 + hl2) * LL + cc * CL + CL - 1];
    }
    __syncthreads();

    size_t base = (size_t)sid * NC * (HD * 16) + p * 16;
    float hs[16], nxt[16];
#pragma unroll
    for (int n = 0; n < 16; n++) { hs[n] = 0.f; nxt[n] = g_S[base + n]; }

    for (int c = 0; c < NC; c++) {
        size_t off = base + (size_t)c * (HD * 16);
#pragma unroll
        for (int n = 0; n < 16; n++) g_hin[off + n] = hs[n];
        float cur[16];
#pragma unroll
        for (int n = 0; n < 16; n++) cur[n] = nxt[n];
        if (c + 1 < NC) {
            size_t off2 = off + HD * 16;
#pragma unroll
            for (int n = 0; n < 16; n++) nxt[n] = g_S[off2 + n];
        }
        float Pt = sP[hl][c];
#pragma unroll
        for (int n = 0; n < 16; n++) hs[n] = fmaf(hs[n], Pt, cur[n]);
    }
}

// ---------------- scan pass 3: 2 heads per block; y += P * (C . h_in) ----------------
__global__ __launch_bounds__(128)
void fixup_k()
{
    int blk  = blockIdx.x;              // 2*8*8*15 = 1920
    int cm   = blk % (NC - 1);
    int rest = blk / (NC - 1);          // 128
    int hp   = rest & 7;
    int b    = (rest >> 3) & 7;
    int d    = rest >> 6;
    int c    = cm + 1;
    int tid  = threadIdx.x;
    int hl   = tid >> 6, p = tid & 63;
    int h    = hp * 2 + hl;
    int sid  = d * 128 + b * 16 + h;
    long base0 = (long)d * MT + (long)b * LL;

    size_t off = ((size_t)sid * NC + c) * (HD * 16) + p * 16;
    float hin[16];
#pragma unroll
    for (int n = 0; n < 16; n++) hin[n] = g_hin[off + n];

    __shared__ float sC[4][16];   // shared across both heads
    __shared__ float sP[2][4];
    int s0 = c * CL;
    int sid0 = d * 128 + b * 16 + hp * 2;   // P for head hl: sid0 + hl  (P identical per head? no!)

    for (int i = 0; i < CL; i += 4) {
        if (tid < 64) {
            int tsub = p >> 4, n = p & 15;
            int s = s0 + i + tsub;
            int t = (d == 0) ? s : (LL - 1 - s);
            sC[tsub][n] = g_xbc[(base0 + t) * (long)CD + DI + 16 + n];
        } else if (tid < 72) {
            int k = tid - 64;          // 0..7: 2 heads x 4 steps
            int hl2 = k >> 2, tsub = k & 3;
            sP[hl2][tsub] = g_P[(size_t)(sid0 + hl2) * LL + s0 + i + tsub];
        }
        __syncthreads();
        float av[4];
#pragma unroll
        for (int j = 0; j < 4; j++) {
            float y = 0.f;
#pragma unroll
            for (int n = 0; n < 16; n++) y = fmaf(hin[n], sC[j][n], y);
            av[j] = y;
        }
#pragma unroll
        for (int j = 0; j < 4; j++) {
            int s = s0 + i + j;
            int t = (d == 0) ? s : (LL - 1 - s);
            long row = base0 + t;
            g_y[row * (long)DI + h * HD + p] += sP[hl][j] * av[j];
        }
        __syncthreads();
    }
}

// ---------------- gated RMSNorm (z from fp16, writes fp16 for gemm_out) ----------------
__global__ __launch_bounds__(256)
void gnorm_k(const float* __restrict__ nwF, const float* __restrict__ nwB)
{
    long r = blockIdx.x;
    int  d = (int)(r / MT);
    const float* nw = (d == 0) ? nwF : nwB;
    const float*  yp = g_y   + r * (long)DI;
    const __half* zp = g_zxh + r * (long)DIP;

    int i0 = threadIdx.x * 4;
    __half2 z01 = *(const __half2*)&zp[i0];
    __half2 z23 = *(const __half2*)&zp[i0 + 2];
    float zf[4] = { __low2float(z01), __high2float(z01),
                    __low2float(z23), __high2float(z23) };
    float v[4];
    float ss = 0.f;
#pragma unroll
    for (int j = 0; j < 4; j++) {
        float val = yp[i0 + j] * siluf(zf[j]);
        v[j] = val;
        ss = fmaf(val, val, ss);
    }
#pragma unroll
    for (int off = 16; off; off >>= 1) ss += __shfl_xor_sync(~0u, ss, off);
    __shared__ float ws[8];
    if ((threadIdx.x & 31) == 0) ws[threadIdx.x >> 5] = ss;
    __syncthreads();
    float tot = ws[0] + ws[1] + ws[2] + ws[3] + ws[4] + ws[5] + ws[6] + ws[7];
    float scale = rsqrtf(tot * (1.f / 1024.f) + 1e-5f);
    float o0 = v[0] * scale * nw[i0 + 0];
    float o1 = v[1] * scale * nw[i0 + 1];
    float o2 = v[2] * scale * nw[i0 + 2];
    float o3 = v[3] * scale * nw[i0 + 3];
    __half2* dst = (__half2*)&g_gh[r * (long)DI + i0];
    dst[0] = __floats2half2_rn(o0, o1);
    dst[1] = __floats2half2_rn(o2, o3);
}

// ---------------- launch ----------------
extern "C" void kernel_launch(void* const* d_in, const int* in_sizes, int n_in,
                              void* d_out, int out_size)
{
    const float* x    = (const float*)d_in[0];
    const float* ipwF = (const float*)d_in[1];
    const float* cwF  = (const float*)d_in[2];
    const float* cbF  = (const float*)d_in[3];
    const float* dbF  = (const float*)d_in[4];
    const float* alF  = (const float*)d_in[5];
    const float* dpF  = (const float*)d_in[6];
    const float* nwF  = (const float*)d_in[7];
    const float* opF  = (const float*)d_in[8];
    const float* ipwB = (const float*)d_in[9];
    const float* cwB  = (const float*)d_in[10];
    const float* cbB  = (const float*)d_in[11];
    const float* dbB  = (const float*)d_in[12];
    const float* alB  = (const float*)d_in[13];
    const float* dpB  = (const float*)d_in[14];
    const float* nwB  = (const float*)d_in[15];
    const float* opB  = (const float*)d_in[16];
    float* out = (float*)d_out;

    __half *zxh_d, *xh_d, *wih_d, *woh_d, *gh_d;
    cudaGetSymbolAddress((void**)&zxh_d, g_zxh);
    cudaGetSymbolAddress((void**)&xh_d,  g_xh);
    cudaGetSymbolAddress((void**)&wih_d, g_wih);
    cudaGetSymbolAddress((void**)&woh_d, g_woh);
    cudaGetSymbolAddress((void**)&gh_d,  g_gh);

    cudaFuncSetAttribute((const void*)gemm_in,
                         cudaFuncAttributeMaxDynamicSharedMemorySize, GEMM_SMEM);
    cudaFuncSetAttribute((const void*)gemm_out,
                         cudaFuncAttributeMaxDynamicSharedMemorySize, GEMM_SMEM);

    // 0) fp32 -> fp16 conversions (one launch)
    {
        int total = N4_X + 2 * N4_WI + 2 * N4_WO;
        tohalf_all<<<(total + 255) / 256, 256>>>(
            (const float4*)x, (const float4*)ipwF, (const float4*)ipwB,
            (const float4*)opF, (const float4*)opB,
            (__half2*)xh_d, (__half2*)wih_d, (__half2*)woh_d);
    }

    // 1) in_proj both directions + fused dadt tail blocks (x = 17)
    gemm_in<<<dim3(18, 128, 2), 256, GEMM_SMEM>>>(
        xh_d, wih_d, wih_d + (size_t)DIP * DM, zxh_d,
        x, ipwF, ipwB, dbF, alF, dbB, alB);

    // 2) depthwise conv + silu for B/C channels only
    conv_bc_k<<<256, 256>>>(cwF, cbF, cwB, cbB);

    // 3) chunked selective scan (fused x-conv; 2 heads per block)
    chunk_scan_k<<<NSCAN * NC / 2, 128>>>(dpF, dpB, cwF, cbF, cwB, cbB);
    state_scan_k<<<NSCAN / 2, 128>>>();
    fixup_k<<<(NSCAN / 2) * (NC - 1), 128>>>();

    // 4) gated RMSNorm (fp16 z in, fp16 out)
    gnorm_k<<<2 * MT, 256>>>(nwF, nwB);

    // 5) out_proj: single fp16 GEMM, K-concat fwd+bwd
    gemm_out<<<dim3(4, 128), 256, GEMM_SMEM>>>(
        gh_d, gh_d + (size_t)MT * DI,
        woh_d, woh_d + (size_t)DM * DI, out);
}

// round 16
// speedup vs baseline: 1.0246x; 1.0246x over previous
#include <cuda_runtime.h>
#include <cuda_fp16.h>
#include <math.h>
#include <stdint.h>

#define BB 8
#define LL 2048
#define DM 512
#define DI 1024
#define NH 16
#define HD 64
#define CD 1056
#define DIP 2096
#define MT (BB*LL)      // 16384 tokens
#define CL 128          // scan chunk length
#define NC (LL/CL)      // 16 chunks
#define NSCAN 256       // 2 dirs * 8 batch * 16 heads

// ---------------- scratch (static device globals; no allocation) ----------------
__device__ __half g_zxh[2ull*MT*DIP];       // in_proj output in fp16
__device__ float  g_xbc[2ull*MT*CD];        // only BC region [DI, DI+32) used
__device__ float  g_dt [2ull*MT*NH];
__device__ float  g_dA [2ull*MT*NH];
__device__ __half g_yh [2ull*MT*DI];        // scan output in fp16
__device__ float  g_P  [(size_t)NSCAN*LL];
__device__ float  g_S  [(size_t)NSCAN*NC*HD*16];
__device__ float  g_hin[(size_t)NSCAN*NC*HD*16];
__device__ __half g_xh [(size_t)MT*DM];
__device__ __half g_wih[2ull*DIP*DM];
__device__ __half g_woh[2ull*DM*DI];
__device__ __half g_gh [2ull*MT*DI];

__device__ __forceinline__ float siluf(float v)     { return v / (1.f + expf(-v)); }
__device__ __forceinline__ float softplusf(float v) { return fmaxf(v, 0.f) + log1pf(expf(-fabsf(v))); }
__device__ __forceinline__ void mma16(float* c, const uint32_t* a, const uint32_t* b) {
    asm volatile(
        "mma.sync.aligned.m16n8k16.row.col.f32.f16.f16.f32 "
        "{%0,%1,%2,%3}, {%4,%5,%6,%7}, {%8,%9}, {%0,%1,%2,%3};"
        : "+f"(c[0]), "+f"(c[1]), "+f"(c[2]), "+f"(c[3])
        : "r"(a[0]), "r"(a[1]), "r"(a[2]), "r"(a[3]), "r"(b[0]), "r"(b[1]));
}
__device__ __forceinline__ void ldsm4(uint32_t* r, uint32_t addr) {
    asm volatile("ldmatrix.sync.aligned.m8n8.x4.shared.b16 {%0,%1,%2,%3}, [%4];"
        : "=r"(r[0]), "=r"(r[1]), "=r"(r[2]), "=r"(r[3]) : "r"(addr));
}
__device__ __forceinline__ uint32_t s2u32(const void* p) {
    return (uint32_t)__cvta_generic_to_shared(p);
}
__device__ __forceinline__ void cpa16(const void* sp, const void* g) {
    asm volatile("cp.async.cg.shared.global [%0], [%1], 16;" :: "r"(s2u32(sp)), "l"(g));
}
__device__ __forceinline__ void cpa16p(const void* sp, const void* g, bool pred) {
    int sz = pred ? 16 : 0;
    asm volatile("cp.async.cg.shared.global [%0], [%1], 16, %2;" :: "r"(s2u32(sp)), "l"(g), "r"(sz));
}
__device__ __forceinline__ void cpa4(const void* sp, const void* g) {
    asm volatile("cp.async.ca.shared.global [%0], [%1], 4;" :: "r"(s2u32(sp)), "l"(g));
}
#define CP_COMMIT() asm volatile("cp.async.commit_group;" ::: "memory")
#define CP_WAIT(n)  asm volatile("cp.async.wait_group %0;" :: "n"(n) : "memory")

// ---------------- fp32 -> fp16 conversion prep (single launch, 5 regions) ----------------
#define N4_X  (MT*DM/4)
#define N4_WI (DIP*DM/4)
#define N4_WO (DM*DI/4)
__global__ __launch_bounds__(256)
void tohalf_all(const float4* __restrict__ x,
                const float4* __restrict__ wF, const float4* __restrict__ wB,
                const float4* __restrict__ oF, const float4* __restrict__ oB,
                __half2* __restrict__ xh, __half2* __restrict__ wih,
                __half2* __restrict__ woh)
{
    int i = blockIdx.x * 256 + threadIdx.x;
    const float4* s; __half2* d; int li;
    if (i < N4_X)                    { s = x;  d = xh;                li = i; }
    else if (i < N4_X + N4_WI)       { s = wF; d = wih;               li = i - N4_X; }
    else if (i < N4_X + 2*N4_WI)     { s = wB; d = wih + N4_WI*2;     li = i - N4_X - N4_WI; }
    else if (i < N4_X + 2*N4_WI + N4_WO) { s = oF; d = woh;           li = i - N4_X - 2*N4_WI; }
    else if (i < N4_X + 2*N4_WI + 2*N4_WO) { s = oB; d = woh + N4_WO*2; li = i - N4_X - 2*N4_WI - N4_WO; }
    else return;
    float4 v = s[li];
    d[2*li]   = __floats2half2_rn(v.x, v.y);
    d[2*li+1] = __floats2half2_rn(v.z, v.w);
}

// ============================================================================
// fp16 GEMM (BM=128, BN=128, BK=32; 8 warps 2x4, warp tile 64x32), 3-stage,
// ldmatrix fragment loads. smem row stride 40 halfs (80B), conflict-free.
// ============================================================================
#define GEMM_SMEM 61440
#define ASMD(st,r,kh) ((void*)(sAh + (((st)*128 + (r))*40 + (kh))))
#define BSMD(st,r,kh) ((void*)(sBh + (((st)*128 + (r))*40 + (kh))))

#define GEMM_PROLOGUE \
    extern __shared__ __align__(16) char smraw[]; \
    __half* sAh = (__half*)smraw; \
    __half* sBh = (__half*)(smraw + 3*128*80); \
    const uint32_t sA32 = s2u32(sAh); \
    const uint32_t sB32 = s2u32(sBh); \
    const int tid  = threadIdx.x; \
    const int lane = tid & 31; \
    const int wid  = tid >> 5; \
    const int mw   = wid & 1; \
    const int nw   = wid >> 1; \
    const int g = lane >> 2; \
    const int q = lane & 3; \
    const int r8  = lane & 7; \
    const int sub = lane >> 3; \
    float acc[4][4][4]; \
    _Pragma("unroll") for (int i = 0; i < 4; i++) \
    _Pragma("unroll") for (int j = 0; j < 4; j++) \
    _Pragma("unroll") for (int r = 0; r < 4; r++) acc[i][j][r] = 0.f;

#define GEMM_COMPUTE(cur) \
    { \
      const uint32_t abase = sA32 + (uint32_t)((((cur)*128 + mw*64 + (sub&1)*8 + r8)*40 + (sub>>1)*8)*2); \
      const uint32_t bbase = sB32 + (uint32_t)((((cur)*128 + nw*32 + (sub>>1)*8 + r8)*40 + (sub&1)*8)*2); \
      _Pragma("unroll") \
      for (int kk = 0; kk < 32; kk += 16) { \
        uint32_t af[4][4], bp0[4], bp1[4]; \
        _Pragma("unroll") \
        for (int mt = 0; mt < 4; mt++) ldsm4(af[mt], abase + mt*(16*80) + kk*2); \
        ldsm4(bp0, bbase + kk*2); \
        ldsm4(bp1, bbase + 16*80 + kk*2); \
        _Pragma("unroll") \
        for (int mt = 0; mt < 4; mt++) { \
            mma16(acc[mt][0], af[mt], bp0); \
            mma16(acc[mt][1], af[mt], bp0 + 2); \
            mma16(acc[mt][2], af[mt], bp1); \
            mma16(acc[mt][3], af[mt], bp1 + 2); \
        } \
      } \
    }

#define GEMM_MAINLOOP(T) \
    load_tile(0, 0); CP_COMMIT(); \
    load_tile(1, 1); CP_COMMIT(); \
    load_tile(2, 2); CP_COMMIT(); \
    for (int kt = 0; kt < (T); kt++) { \
        const int cur = kt % 3; \
        if (kt + 2 < (T)) { CP_WAIT(2); } \
        else if (kt + 1 < (T)) { CP_WAIT(1); } \
        else { CP_WAIT(0); } \
        __syncthreads(); \
        GEMM_COMPUTE(cur) \
        __syncthreads(); \
        if (kt + 3 < (T)) { load_tile(kt + 3, cur); CP_COMMIT(); } \
    }

// ---------------- in_proj (+ fused dadt tail blocks): grid (18,128,2) ----------------
__global__ void __launch_bounds__(256, 2)
gemm_in(const __half* __restrict__ Ah, const __half* __restrict__ Bh0,
        const __half* __restrict__ Bh1, __half* __restrict__ Cb,
        const float* __restrict__ x,
        const float* __restrict__ ipwF, const float* __restrict__ ipwB,
        const float* __restrict__ dbF,  const float* __restrict__ alF,
        const float* __restrict__ dbB,  const float* __restrict__ alB)
{
    if (blockIdx.x == 17) {
        extern __shared__ __align__(16) char smraw[];
        float (*sW)[512] = (float(*)[512])smraw;
        const int d  = blockIdx.z;
        const int tb = blockIdx.y;
        const int tid = threadIdx.x;
        const float* W = (d ? ipwB : ipwF) + (size_t)(DI + CD) * DM;
#pragma unroll
        for (int j = 0; j < 8; j++)
            ((float4*)&sW[0][0])[j * 256 + tid] = ((const float4*)W)[j * 256 + tid];
        __syncthreads();

        const int h = tid >> 4, l = tid & 15;
        const float db = (d ? dbB : dbF)[h];
        const float Av = -expf((d ? alB : alF)[h]);

        for (int tk = 0; tk < 128; tk++) {
            int token = tb * 128 + tk;
            const float4* xr = (const float4*)(x + (size_t)token * DM);
            const float4* wr = (const float4*)&sW[h][0];
            float s = 0.f;
#pragma unroll
            for (int j = 0; j < 8; j++) {
                float4 xv = xr[l + 16 * j];
                float4 wv = wr[l + 16 * j];
                s = fmaf(xv.x, wv.x, s); s = fmaf(xv.y, wv.y, s);
                s = fmaf(xv.z, wv.z, s); s = fmaf(xv.w, wv.w, s);
            }
            s += __shfl_xor_sync(~0u, s, 1);
            s += __shfl_xor_sync(~0u, s, 2);
            s += __shfl_xor_sync(~0u, s, 4);
            s += __shfl_xor_sync(~0u, s, 8);
            if (l == 0) {
                float dt = softplusf(s + db);
                size_t r = (size_t)d * MT + token;
                g_dt[r * NH + h] = dt;
                g_dA[r * NH + h] = expf(dt * Av);
            }
        }
        return;
    }

    const __half* B = blockIdx.z ? Bh1 : Bh0;
    __half* C = Cb + (size_t)blockIdx.z * MT * DIP;
    const int m0 = blockIdx.y * 128, n0 = blockIdx.x * 128;
    const int N = DIP, K = DM;

    GEMM_PROLOGUE

    auto load_tile = [&](int kt, int buf) {
        const int k0 = kt << 5;
#pragma unroll
        for (int i = 0; i < 2; i++) {
            int id  = tid + (i << 8);
            int row = id >> 2;
            int seg = (id & 3) << 3;
            cpa16(ASMD(buf, row, seg), Ah + (size_t)(m0 + row) * K + k0 + seg);
            cpa16p(BSMD(buf, row, seg), B + (size_t)(n0 + row) * K + k0 + seg,
                   (n0 + row) < N);
        }
    };

    GEMM_MAINLOOP(K >> 5)

#pragma unroll
    for (int mt = 0; mt < 4; mt++) {
        int row = m0 + mw * 64 + mt * 16 + g;
#pragma unroll
        for (int nt = 0; nt < 4; nt++) {
            int n = n0 + nw * 32 + nt * 8 + q * 2;
            if (n < N) {
                *(__half2*)(C + (size_t)row * DIP + n) =
                    __floats2half2_rn(acc[mt][nt][0], acc[mt][nt][1]);
                *(__half2*)(C + (size_t)(row + 8) * DIP + n) =
                    __floats2half2_rn(acc[mt][nt][2], acc[mt][nt][3]);
            }
        }
    }
}

// ---------------- out_proj: K-concat of fwd+bwd (K=2048) -> single write ----------------
__global__ void __launch_bounds__(256, 2)
gemm_out(const __half* __restrict__ A0, const __half* __restrict__ A1,
         const __half* __restrict__ B0, const __half* __restrict__ B1,
         float* __restrict__ C)
{
    const int m0 = blockIdx.y * 128, n0 = blockIdx.x * 128;
    const int K = 2 * DI;

    GEMM_PROLOGUE

    auto load_tile = [&](int kt, int buf) {
        const int k0 = kt << 5;
        const __half* Ap; const __half* Bp; int kl;
        if (k0 < DI) { Ap = A0; Bp = B0; kl = k0; }
        else         { Ap = A1; Bp = B1; kl = k0 - DI; }
#pragma unroll
        for (int i = 0; i < 2; i++) {
            int id  = tid + (i << 8);
            int row = id >> 2;
            int seg = (id & 3) << 3;
            cpa16(ASMD(buf, row, seg), Ap + (size_t)(m0 + row) * DI + kl + seg);
            cpa16(BSMD(buf, row, seg), Bp + (size_t)(n0 + row) * DI + kl + seg);
        }
    };

    GEMM_MAINLOOP(K >> 5)

#pragma unroll
    for (int mt = 0; mt < 4; mt++) {
        int row = m0 + mw * 64 + mt * 16 + g;
#pragma unroll
        for (int nt = 0; nt < 4; nt++) {
            int n = n0 + nw * 32 + nt * 8 + q * 2;
            *(float2*)(C + (size_t)row * DM + n) =
                make_float2(acc[mt][nt][0], acc[mt][nt][1]);
            *(float2*)(C + (size_t)(row + 8) * DM + n) =
                make_float2(acc[mt][nt][2], acc[mt][nt][3]);
        }
    }
}

// ---------------- depthwise conv(4) + bias + SiLU — B/C channels only ----------------
#define CTT 16
__global__ __launch_bounds__(256)
void conv_bc_k(const float* __restrict__ cwF, const float* __restrict__ cbF,
               const float* __restrict__ cwB, const float* __restrict__ cbB)
{
    int idx = blockIdx.x * 256 + threadIdx.x;
    int  c  = DI + (idx & 31);
    int  q2 = idx >> 5;
    int  tg = q2 & (LL / CTT - 1);
    int  bd = q2 >> 7;
    int  b  = bd & 7, d = bd >> 3;
    int  t0 = tg * CTT;

    const float* wv = (d == 0 ? cwF : cwB) + c * 4;
    float w0 = wv[0], w1 = wv[1], w2 = wv[2], w3 = wv[3];
    float bias = (d == 0 ? cbF : cbB)[c];
    long rbase = (long)d * MT + (long)b * LL;
    const __half* zin = g_zxh + rbase * (long)DIP + DI + c;
    float* outp = g_xbc + (rbase + t0) * (long)CD + c;

    float in[CTT + 3];
    if (d == 0) {
#pragma unroll
        for (int j = 0; j < CTT + 3; j++) {
            int tt = t0 - 3 + j;
            in[j] = (tt >= 0) ? __half2float(zin[(long)tt * DIP]) : 0.f;
        }
#pragma unroll
        for (int i = 0; i < CTT; i++) {
            float a = bias;
            a = fmaf(w0, in[i], a); a = fmaf(w1, in[i+1], a);
            a = fmaf(w2, in[i+2], a); a = fmaf(w3, in[i+3], a);
            outp[(long)i * CD] = siluf(a);
        }
    } else {
#pragma unroll
        for (int j = 0; j < CTT + 3; j++) {
            int tt = t0 + j;
            in[j] = (tt < LL) ? __half2float(zin[(long)tt * DIP]) : 0.f;
        }
#pragma unroll
        for (int i = 0; i < CTT; i++) {
            float a = bias;
            a = fmaf(w3, in[i], a); a = fmaf(w2, in[i+1], a);
            a = fmaf(w1, in[i+2], a); a = fmaf(w0, in[i+3], a);
            outp[(long)i * CD] = siluf(a);
        }
    }
}

// ---------------- scan pass 1: chunk scans with FUSED x-conv+SiLU (64 thr) ----------------
__global__ __launch_bounds__(64)
void chunk_scan_k(const float* __restrict__ DpF, const float* __restrict__ DpB,
                  const float* __restrict__ cwF, const float* __restrict__ cbF,
                  const float* __restrict__ cwB, const float* __restrict__ cbB)
{
    int blk = blockIdx.x;
    int c   = blk & (NC - 1);
    int sid = blk >> 4;
    int d = sid >> 7, b = (sid >> 4) & 7, h = sid & 15;
    int p = threadIdx.x;

    __shared__ float  sBC[2][8][36];   // B16,C16,dt,dA per step
    __shared__ __half sZ [2][11][64];  // 8 steps + 3 halo of z rows
    float hs[16];
#pragma unroll
    for (int n = 0; n < 16; n++) hs[n] = 0.f;
    float dp = (d == 0 ? DpF : DpB)[h];
    long base0 = (long)d * MT + (long)b * LL;
    int s0 = c * CL;

    const int ch = h * HD + p;
    const float* wv = (d == 0 ? cwF : cwB) + ch * 4;
    const float w0 = wv[0], w1 = wv[1], w2 = wv[2], w3 = wv[3];
    const float cbias = (d == 0 ? cbF : cbB)[ch];

    auto rowof = [&](int s) -> long {
        int t = (d == 0) ? s : (LL - 1 - s);
        return base0 + t;
    };
    auto loadgrp = [&](int gg, int buf) {
        {
            int j = p >> 3, seg = p & 7;
            long row = rowof(s0 + gg * 8 + j);
            cpa16(&sBC[buf][j][seg * 4], &g_xbc[row * (long)CD + DI + seg * 4]);
        }
#pragma unroll
        for (int it = 0; it < 2; it++) {
            int idx2 = p + it * 64;
            if (idx2 < 88) {
                int j = idx2 >> 3, seg = idx2 & 7;
                int t = (d == 0) ? (s0 + gg * 8 - 3 + j)
                                 : (LL - 8 - s0 - gg * 8 + j);
                void* dst = (void*)&sZ[buf][j][seg * 8];
                if ((unsigned)t < (unsigned)LL)
                    cpa16(dst, &g_zxh[(base0 + t) * (long)DIP + DI + h * HD + seg * 8]);
                else
                    *(uint4*)dst = make_uint4(0, 0, 0, 0);
            }
        }
        if (p < 8) {
            long row = rowof(s0 + gg * 8 + p);
            cpa4(&sBC[buf][p][32], &g_dt[row * (long)NH + h]);
        } else if (p < 16) {
            long row = rowof(s0 + gg * 8 + (p - 8));
            cpa4(&sBC[buf][p - 8][33], &g_dA[row * (long)NH + h]);
        }
    };

    loadgrp(0, 0);
    CP_COMMIT();

    float P = 1.f;
    for (int gg = 0; gg < 16; gg++) {
        int buf = gg & 1;
        if (gg + 1 < 16) {
            loadgrp(gg + 1, buf ^ 1);
            CP_COMMIT();
            CP_WAIT(1);
        } else {
            CP_WAIT(0);
        }
        __syncthreads();
#pragma unroll
        for (int j = 0; j < 8; j++) {
            float a = cbias;
            if (d == 0) {
                a = fmaf(w0, __half2float(sZ[buf][j    ][p]), a);
                a = fmaf(w1, __half2float(sZ[buf][j + 1][p]), a);
                a = fmaf(w2, __half2float(sZ[buf][j + 2][p]), a);
                a = fmaf(w3, __half2float(sZ[buf][j + 3][p]), a);
            } else {
                a = fmaf(w3, __half2float(sZ[buf][7 - j ][p]), a);
                a = fmaf(w2, __half2float(sZ[buf][8 - j ][p]), a);
                a = fmaf(w1, __half2float(sZ[buf][9 - j ][p]), a);
                a = fmaf(w0, __half2float(sZ[buf][10 - j][p]), a);
            }
            float xv = siluf(a);

            float dtv = sBC[buf][j][32], dAv = sBC[buf][j][33];
            float coef = dtv * xv;
            float y = 0.f;
#pragma unroll
            for (int n = 0; n < 16; n += 2) {
                float2 Bn = *(const float2*)&sBC[buf][j][n];
                float2 Cn = *(const float2*)&sBC[buf][j][16 + n];
                hs[n]   = fmaf(hs[n],   dAv, coef * Bn.x);
                y       = fmaf(hs[n],   Cn.x, y);
                hs[n+1] = fmaf(hs[n+1], dAv, coef * Bn.y);
                y       = fmaf(hs[n+1], Cn.y, y);
            }
            P *= dAv;
            int s = s0 + gg * 8 + j;
            g_yh[rowof(s) * (long)DI + h * HD + p] = __float2half(fmaf(dp, xv, y));
            if (p == 0) g_P[(size_t)sid * LL + s] = P;
        }
        __syncthreads();
    }

    float* Sp = g_S + (size_t)blk * (HD * 16) + p * 16;
#pragma unroll
    for (int n = 0; n < 16; n++) Sp[n] = hs[n];
}

// ---------------- scan pass 2: chunk-state propagation, prefetched ----------------
__global__ __launch_bounds__(64)
void state_scan_k()
{
    int sid = blockIdx.x;
    int p = threadIdx.x;
    __shared__ float sP[16];
    if (p < 16) sP[p] = g_P[(size_t)sid * LL + p * CL + CL - 1];
    __syncthreads();

    size_t base = (size_t)sid * NC * (HD * 16) + p * 16;
    float hs[16], nxt[16];
#pragma unroll
    for (int n = 0; n < 16; n++) { hs[n] = 0.f; nxt[n] = g_S[base + n]; }

    for (int c = 0; c < NC; c++) {
        size_t off = base + (size_t)c * (HD * 16);
#pragma unroll
        for (int n = 0; n < 16; n++) g_hin[off + n] = hs[n];
        float cur[16];
#pragma unroll
        for (int n = 0; n < 16; n++) cur[n] = nxt[n];
        if (c + 1 < NC) {
            size_t off2 = off + HD * 16;
#pragma unroll
            for (int n = 0; n < 16; n++) nxt[n] = g_S[off2 + n];
        }
        float Pt = sP[c];
#pragma unroll
        for (int n = 0; n < 16; n++) hs[n] = fmaf(hs[n], Pt, cur[n]);
    }
}

// ---------------- scan pass 3: y[s] += P[s] * (C[s] . h_in)  (fp16 RMW) ----------------
__global__ __launch_bounds__(64)
void fixup_k()
{
    int blk = blockIdx.x;
    int cm  = blk % (NC - 1);
    int sid = blk / (NC - 1);
    int c   = cm + 1;
    int d = sid >> 7, b = (sid >> 4) & 7, h = sid & 15;
    int p = threadIdx.x;
    long base0 = (long)d * MT + (long)b * LL;

    size_t off = ((size_t)sid * NC + c) * (HD * 16) + p * 16;
    float hin[16];
#pragma unroll
    for (int n = 0; n < 16; n++) hin[n] = g_hin[off + n];

    __shared__ float sC[4][16];
    __shared__ float sP[4];
    int s0 = c * CL;

    for (int i = 0; i < CL; i += 4) {
        {
            int tsub = p >> 4, n = p & 15;
            int s = s0 + i + tsub;
            int t = (d == 0) ? s : (LL - 1 - s);
            sC[tsub][n] = g_xbc[(base0 + t) * (long)CD + DI + 16 + n];
            if (n == 0) sP[tsub] = g_P[(size_t)sid * LL + s];
        }
        __syncthreads();
        float av[4];
#pragma unroll
        for (int j = 0; j < 4; j++) {
            float y = 0.f;
#pragma unroll
            for (int n = 0; n < 16; n++) y = fmaf(hin[n], sC[j][n], y);
            av[j] = y;
        }
#pragma unroll
        for (int j = 0; j < 4; j++) {
            int s = s0 + i + j;
            int t = (d == 0) ? s : (LL - 1 - s);
            __half* yp = &g_yh[(base0 + t) * (long)DI + h * HD + p];
            *yp = __float2half(__half2float(*yp) + sP[j] * av[j]);
        }
        __syncthreads();
    }
}

// ---------------- gated RMSNorm (y + z from fp16, writes fp16 for gemm_out) ----------------
__global__ __launch_bounds__(256)
void gnorm_k(const float* __restrict__ nwF, const float* __restrict__ nwB)
{
    long r = blockIdx.x;
    int  d = (int)(r / MT);
    const float* nw = (d == 0) ? nwF : nwB;
    const __half* yp = g_yh  + r * (long)DI;
    const __half* zp = g_zxh + r * (long)DIP;

    int i0 = threadIdx.x * 4;
    __half2 y01 = *(const __half2*)&yp[i0];
    __half2 y23 = *(const __half2*)&yp[i0 + 2];
    __half2 z01 = *(const __half2*)&zp[i0];
    __half2 z23 = *(const __half2*)&zp[i0 + 2];
    float yf[4] = { __low2float(y01), __high2float(y01),
                    __low2float(y23), __high2float(y23) };
    float zf[4] = { __low2float(z01), __high2float(z01),
                    __low2float(z23), __high2float(z23) };
    float v[4];
    float ss = 0.f;
#pragma unroll
    for (int j = 0; j < 4; j++) {
        float val = yf[j] * siluf(zf[j]);
        v[j] = val;
        ss = fmaf(val, val, ss);
    }
#pragma unroll
    for (int off = 16; off; off >>= 1) ss += __shfl_xor_sync(~0u, ss, off);
    __shared__ float ws[8];
    if ((threadIdx.x & 31) == 0) ws[threadIdx.x >> 5] = ss;
    __syncthreads();
    float tot = ws[0] + ws[1] + ws[2] + ws[3] + ws[4] + ws[5] + ws[6] + ws[7];
    float scale = rsqrtf(tot * (1.f / 1024.f) + 1e-5f);
    float o0 = v[0] * scale * nw[i0 + 0];
    float o1 = v[1] * scale * nw[i0 + 1];
    float o2 = v[2] * scale * nw[i0 + 2];
    float o3 = v[3] * scale * nw[i0 + 3];
    __half2* dst = (__half2*)&g_gh[r * (long)DI + i0];
    dst[0] = __floats2half2_rn(o0, o1);
    dst[1] = __floats2half2_rn(o2, o3);
}

// ---------------- launch ----------------
extern "C" void kernel_launch(void* const* d_in, const int* in_sizes, int n_in,
                              void* d_out, int out_size)
{
    const float* x    = (const float*)d_in[0];
    const float* ipwF = (const float*)d_in[1];
    const float* cwF  = (const float*)d_in[2];
    const float* cbF  = (const float*)d_in[3];
    const float* dbF  = (const float*)d_in[4];
    const float* alF  = (const float*)d_in[5];
    const float* dpF  = (const float*)d_in[6];
    const float* nwF  = (const float*)d_in[7];
    const float* opF  = (const float*)d_in[8];
    const float* ipwB = (const float*)d_in[9];
    const float* cwB  = (const float*)d_in[10];
    const float* cbB  = (const float*)d_in[11];
    const float* dbB  = (const float*)d_in[12];
    const float* alB  = (const float*)d_in[13];
    const float* dpB  = (const float*)d_in[14];
    const float* nwB  = (const float*)d_in[15];
    const float* opB  = (const float*)d_in[16];
    float* out = (float*)d_out;

    __half *zxh_d, *xh_d, *wih_d, *woh_d, *gh_d;
    cudaGetSymbolAddress((void**)&zxh_d, g_zxh);
    cudaGetSymbolAddress((void**)&xh_d,  g_xh);
    cudaGetSymbolAddress((void**)&wih_d, g_wih);
    cudaGetSymbolAddress((void**)&woh_d, g_woh);
    cudaGetSymbolAddress((void**)&gh_d,  g_gh);

    cudaFuncSetAttribute((const void*)gemm_in,
                         cudaFuncAttributeMaxDynamicSharedMemorySize, GEMM_SMEM);
    cudaFuncSetAttribute((const void*)gemm_out,
                         cudaFuncAttributeMaxDynamicSharedMemorySize, GEMM_SMEM);

    // 0) fp32 -> fp16 conversions (one launch)
    {
        int total = N4_X + 2 * N4_WI + 2 * N4_WO;
        tohalf_all<<<(total + 255) / 256, 256>>>(
            (const float4*)x, (const float4*)ipwF, (const float4*)ipwB,
            (const float4*)opF, (const float4*)opB,
            (__half2*)xh_d, (__half2*)wih_d, (__half2*)woh_d);
    }

    // 1) in_proj both directions + fused dadt tail blocks (x = 17)
    gemm_in<<<dim3(18, 128, 2), 256, GEMM_SMEM>>>(
        xh_d, wih_d, wih_d + (size_t)DIP * DM, zxh_d,
        x, ipwF, ipwB, dbF, alF, dbB, alB);

    // 2) depthwise conv + silu for B/C channels only
    conv_bc_k<<<256, 256>>>(cwF, cbF, cwB, cbB);

    // 3) chunked selective scan (fused x-conv; fp16 y)
    chunk_scan_k<<<NSCAN * NC, 64>>>(dpF, dpB, cwF, cbF, cwB, cbB);
    state_scan_k<<<NSCAN, 64>>>();
    fixup_k<<<NSCAN * (NC - 1), 64>>>();

    // 4) gated RMSNorm (fp16 y+z in, fp16 out)
    gnorm_k<<<2 * MT, 256>>>(nwF, nwB);

    // 5) out_proj: single fp16 GEMM, K-concat fwd+bwd
    gemm_out<<<dim3(4, 128), 256, GEMM_SMEM>>>(
        gh_d, gh_d + (size_t)MT * DI,
        woh_d, woh_d + (size_t)DM * DI, out);
}

// round 17
// speedup vs baseline: 1.0393x; 1.0144x over previous
#include <cuda_runtime.h>
#include <cuda_fp16.h>
#include <math.h>
#include <stdint.h>

#define BB 8
#define LL 2048
#define DM 512
#define DI 1024
#define NH 16
#define HD 64
#define CD 1056
#define DIP 2096
#define MT (BB*LL)      // 16384 tokens
#define CL 128          // scan chunk length
#define NC (LL/CL)      // 16 chunks
#define NSCAN 256       // 2 dirs * 8 batch * 16 heads

// ---------------- scratch (static device globals; no allocation) ----------------
__device__ __half g_zxh[2ull*MT*DIP];       // in_proj output in fp16
__device__ float  g_xbc[2ull*MT*CD];        // only BC region [DI, DI+32) used
__device__ float  g_dt [2ull*MT*NH];
__device__ float  g_dA [2ull*MT*NH];
__device__ __half g_yh [2ull*MT*DI];        // scan output in fp16
__device__ float  g_P  [(size_t)NSCAN*LL];
__device__ float  g_S  [(size_t)NSCAN*NC*HD*16];
__device__ float  g_hin[(size_t)NSCAN*NC*HD*16];
__device__ __half g_xh [(size_t)MT*DM];
__device__ __half g_wih[2ull*DIP*DM];
__device__ __half g_woh[2ull*DM*DI];
__device__ __half g_gh [2ull*MT*DI];

__device__ __forceinline__ float siluf(float v)     { return v / (1.f + expf(-v)); }
__device__ __forceinline__ float softplusf(float v) { return fmaxf(v, 0.f) + log1pf(expf(-fabsf(v))); }
__device__ __forceinline__ void mma16(float* c, const uint32_t* a, const uint32_t* b) {
    asm volatile(
        "mma.sync.aligned.m16n8k16.row.col.f32.f16.f16.f32 "
        "{%0,%1,%2,%3}, {%4,%5,%6,%7}, {%8,%9}, {%0,%1,%2,%3};"
        : "+f"(c[0]), "+f"(c[1]), "+f"(c[2]), "+f"(c[3])
        : "r"(a[0]), "r"(a[1]), "r"(a[2]), "r"(a[3]), "r"(b[0]), "r"(b[1]));
}
__device__ __forceinline__ void ldsm4(uint32_t* r, uint32_t addr) {
    asm volatile("ldmatrix.sync.aligned.m8n8.x4.shared.b16 {%0,%1,%2,%3}, [%4];"
        : "=r"(r[0]), "=r"(r[1]), "=r"(r[2]), "=r"(r[3]) : "r"(addr));
}
__device__ __forceinline__ uint32_t s2u32(const void* p) {
    return (uint32_t)__cvta_generic_to_shared(p);
}
__device__ __forceinline__ void cpa16(const void* sp, const void* g) {
    asm volatile("cp.async.cg.shared.global [%0], [%1], 16;" :: "r"(s2u32(sp)), "l"(g));
}
__device__ __forceinline__ void cpa16p(const void* sp, const void* g, bool pred) {
    int sz = pred ? 16 : 0;
    asm volatile("cp.async.cg.shared.global [%0], [%1], 16, %2;" :: "r"(s2u32(sp)), "l"(g), "r"(sz));
}
__device__ __forceinline__ void cpa4(const void* sp, const void* g) {
    asm volatile("cp.async.ca.shared.global [%0], [%1], 4;" :: "r"(s2u32(sp)), "l"(g));
}
#define CP_COMMIT() asm volatile("cp.async.commit_group;" ::: "memory")
#define CP_WAIT(n)  asm volatile("cp.async.wait_group %0;" :: "n"(n) : "memory")

// ---------------- fp32 -> fp16 conversion prep (single launch, 5 regions) ----------------
#define N4_X  (MT*DM/4)
#define N4_WI (DIP*DM/4)
#define N4_WO (DM*DI/4)
__global__ __launch_bounds__(256)
void tohalf_all(const float4* __restrict__ x,
                const float4* __restrict__ wF, const float4* __restrict__ wB,
                const float4* __restrict__ oF, const float4* __restrict__ oB,
                __half2* __restrict__ xh, __half2* __restrict__ wih,
                __half2* __restrict__ woh)
{
    int i = blockIdx.x * 256 + threadIdx.x;
    const float4* s; __half2* d; int li;
    if (i < N4_X)                    { s = x;  d = xh;                li = i; }
    else if (i < N4_X + N4_WI)       { s = wF; d = wih;               li = i - N4_X; }
    else if (i < N4_X + 2*N4_WI)     { s = wB; d = wih + N4_WI*2;     li = i - N4_X - N4_WI; }
    else if (i < N4_X + 2*N4_WI + N4_WO) { s = oF; d = woh;           li = i - N4_X - 2*N4_WI; }
    else if (i < N4_X + 2*N4_WI + 2*N4_WO) { s = oB; d = woh + N4_WO*2; li = i - N4_X - 2*N4_WI - N4_WO; }
    else return;
    float4 v = s[li];
    d[2*li]   = __floats2half2_rn(v.x, v.y);
    d[2*li+1] = __floats2half2_rn(v.z, v.w);
}

// ============================================================================
// fp16 GEMM (BM=128, BN=128, BK=32; 8 warps 2x4, warp tile 64x32), 3-stage,
// single-sync mainloop, ldmatrix fragment loads. smem stride 40 halfs (80B).
// ============================================================================
#define GEMM_SMEM 61440
#define ASMD(st,r,kh) ((void*)(sAh + (((st)*128 + (r))*40 + (kh))))
#define BSMD(st,r,kh) ((void*)(sBh + (((st)*128 + (r))*40 + (kh))))

#define GEMM_PROLOGUE \
    extern __shared__ __align__(16) char smraw[]; \
    __half* sAh = (__half*)smraw; \
    __half* sBh = (__half*)(smraw + 3*128*80); \
    const uint32_t sA32 = s2u32(sAh); \
    const uint32_t sB32 = s2u32(sBh); \
    const int tid  = threadIdx.x; \
    const int lane = tid & 31; \
    const int wid  = tid >> 5; \
    const int mw   = wid & 1; \
    const int nw   = wid >> 1; \
    const int g = lane >> 2; \
    const int q = lane & 3; \
    const int r8  = lane & 7; \
    const int sub = lane >> 3; \
    float acc[4][4][4]; \
    _Pragma("unroll") for (int i = 0; i < 4; i++) \
    _Pragma("unroll") for (int j = 0; j < 4; j++) \
    _Pragma("unroll") for (int r = 0; r < 4; r++) acc[i][j][r] = 0.f;

#define GEMM_COMPUTE(cur) \
    { \
      const uint32_t abase = sA32 + (uint32_t)((((cur)*128 + mw*64 + (sub&1)*8 + r8)*40 + (sub>>1)*8)*2); \
      const uint32_t bbase = sB32 + (uint32_t)((((cur)*128 + nw*32 + (sub>>1)*8 + r8)*40 + (sub&1)*8)*2); \
      _Pragma("unroll") \
      for (int kk = 0; kk < 32; kk += 16) { \
        uint32_t af[4][4], bp0[4], bp1[4]; \
        _Pragma("unroll") \
        for (int mt = 0; mt < 4; mt++) ldsm4(af[mt], abase + mt*(16*80) + kk*2); \
        ldsm4(bp0, bbase + kk*2); \
        ldsm4(bp1, bbase + 16*80 + kk*2); \
        _Pragma("unroll") \
        for (int mt = 0; mt < 4; mt++) { \
            mma16(acc[mt][0], af[mt], bp0); \
            mma16(acc[mt][1], af[mt], bp0 + 2); \
            mma16(acc[mt][2], af[mt], bp1); \
            mma16(acc[mt][3], af[mt], bp1 + 2); \
        } \
      } \
    }

// Single-sync multistage: prologue loads tiles 0,1. At iter kt:
//   wait for tile kt, sync (also proves compute(kt-1) done by all),
//   issue load(kt+2) into buffer (kt+2)%3 = (kt-1)%3 (safe), compute(kt).
#define GEMM_MAINLOOP(T) \
    load_tile(0, 0); CP_COMMIT(); \
    load_tile(1, 1); CP_COMMIT(); \
    for (int kt = 0; kt < (T); kt++) { \
        const int cur = kt % 3; \
        if (kt + 1 < (T)) { CP_WAIT(1); } else { CP_WAIT(0); } \
        __syncthreads(); \
        if (kt + 2 < (T)) { load_tile(kt + 2, (kt + 2) % 3); CP_COMMIT(); } \
        GEMM_COMPUTE(cur) \
    }

// ---------------- in_proj (+ fused dadt tail blocks): grid (18,128,2) ----------------
__global__ void __launch_bounds__(256, 2)
gemm_in(const __half* __restrict__ Ah, const __half* __restrict__ Bh0,
        const __half* __restrict__ Bh1, __half* __restrict__ Cb,
        const float* __restrict__ x,
        const float* __restrict__ ipwF, const float* __restrict__ ipwB,
        const float* __restrict__ dbF,  const float* __restrict__ alF,
        const float* __restrict__ dbB,  const float* __restrict__ alB)
{
    if (blockIdx.x == 17) {
        extern __shared__ __align__(16) char smraw[];
        float (*sW)[512] = (float(*)[512])smraw;
        const int d  = blockIdx.z;
        const int tb = blockIdx.y;
        const int tid = threadIdx.x;
        const float* W = (d ? ipwB : ipwF) + (size_t)(DI + CD) * DM;
#pragma unroll
        for (int j = 0; j < 8; j++)
            ((float4*)&sW[0][0])[j * 256 + tid] = ((const float4*)W)[j * 256 + tid];
        __syncthreads();

        const int h = tid >> 4, l = tid & 15;
        const float db = (d ? dbB : dbF)[h];
        const float Av = -expf((d ? alB : alF)[h]);

        for (int tk = 0; tk < 128; tk++) {
            int token = tb * 128 + tk;
            const float4* xr = (const float4*)(x + (size_t)token * DM);
            const float4* wr = (const float4*)&sW[h][0];
            float s = 0.f;
#pragma unroll
            for (int j = 0; j < 8; j++) {
                float4 xv = xr[l + 16 * j];
                float4 wv = wr[l + 16 * j];
                s = fmaf(xv.x, wv.x, s); s = fmaf(xv.y, wv.y, s);
                s = fmaf(xv.z, wv.z, s); s = fmaf(xv.w, wv.w, s);
            }
            s += __shfl_xor_sync(~0u, s, 1);
            s += __shfl_xor_sync(~0u, s, 2);
            s += __shfl_xor_sync(~0u, s, 4);
            s += __shfl_xor_sync(~0u, s, 8);
            if (l == 0) {
                float dt = softplusf(s + db);
                size_t r = (size_t)d * MT + token;
                g_dt[r * NH + h] = dt;
                g_dA[r * NH + h] = expf(dt * Av);
            }
        }
        return;
    }

    const __half* B = blockIdx.z ? Bh1 : Bh0;
    __half* C = Cb + (size_t)blockIdx.z * MT * DIP;
    const int m0 = blockIdx.y * 128, n0 = blockIdx.x * 128;
    const int N = DIP, K = DM;

    GEMM_PROLOGUE

    auto load_tile = [&](int kt, int buf) {
        const int k0 = kt << 5;
#pragma unroll
        for (int i = 0; i < 2; i++) {
            int id  = tid + (i << 8);
            int row = id >> 2;
            int seg = (id & 3) << 3;
            cpa16(ASMD(buf, row, seg), Ah + (size_t)(m0 + row) * K + k0 + seg);
            cpa16p(BSMD(buf, row, seg), B + (size_t)(n0 + row) * K + k0 + seg,
                   (n0 + row) < N);
        }
    };

    GEMM_MAINLOOP(K >> 5)

#pragma unroll
    for (int mt = 0; mt < 4; mt++) {
        int row = m0 + mw * 64 + mt * 16 + g;
#pragma unroll
        for (int nt = 0; nt < 4; nt++) {
            int n = n0 + nw * 32 + nt * 8 + q * 2;
            if (n < N) {
                *(__half2*)(C + (size_t)row * DIP + n) =
                    __floats2half2_rn(acc[mt][nt][0], acc[mt][nt][1]);
                *(__half2*)(C + (size_t)(row + 8) * DIP + n) =
                    __floats2half2_rn(acc[mt][nt][2], acc[mt][nt][3]);
            }
        }
    }
}

// ---------------- out_proj: K-concat of fwd+bwd (K=2048) -> single write ----------------
__global__ void __launch_bounds__(256, 2)
gemm_out(const __half* __restrict__ A0, const __half* __restrict__ A1,
         const __half* __restrict__ B0, const __half* __restrict__ B1,
         float* __restrict__ C)
{
    const int m0 = blockIdx.y * 128, n0 = blockIdx.x * 128;
    const int K = 2 * DI;

    GEMM_PROLOGUE

    auto load_tile = [&](int kt, int buf) {
        const int k0 = kt << 5;
        const __half* Ap; const __half* Bp; int kl;
        if (k0 < DI) { Ap = A0; Bp = B0; kl = k0; }
        else         { Ap = A1; Bp = B1; kl = k0 - DI; }
#pragma unroll
        for (int i = 0; i < 2; i++) {
            int id  = tid + (i << 8);
            int row = id >> 2;
            int seg = (id & 3) << 3;
            cpa16(ASMD(buf, row, seg), Ap + (size_t)(m0 + row) * DI + kl + seg);
            cpa16(BSMD(buf, row, seg), Bp + (size_t)(n0 + row) * DI + kl + seg);
        }
    };

    GEMM_MAINLOOP(K >> 5)

#pragma unroll
    for (int mt = 0; mt < 4; mt++) {
        int row = m0 + mw * 64 + mt * 16 + g;
#pragma unroll
        for (int nt = 0; nt < 4; nt++) {
            int n = n0 + nw * 32 + nt * 8 + q * 2;
            *(float2*)(C + (size_t)row * DM + n) =
                make_float2(acc[mt][nt][0], acc[mt][nt][1]);
            *(float2*)(C + (size_t)(row + 8) * DM + n) =
                make_float2(acc[mt][nt][2], acc[mt][nt][3]);
        }
    }
}

// ---------------- depthwise conv(4) + bias + SiLU — B/C channels only ----------------
#define CTT 16
__global__ __launch_bounds__(256)
void conv_bc_k(const float* __restrict__ cwF, const float* __restrict__ cbF,
               const float* __restrict__ cwB, const float* __restrict__ cbB)
{
    int idx = blockIdx.x * 256 + threadIdx.x;
    int  c  = DI + (idx & 31);
    int  q2 = idx >> 5;
    int  tg = q2 & (LL / CTT - 1);
    int  bd = q2 >> 7;
    int  b  = bd & 7, d = bd >> 3;
    int  t0 = tg * CTT;

    const float* wv = (d == 0 ? cwF : cwB) + c * 4;
    float w0 = wv[0], w1 = wv[1], w2 = wv[2], w3 = wv[3];
    float bias = (d == 0 ? cbF : cbB)[c];
    long rbase = (long)d * MT + (long)b * LL;
    const __half* zin = g_zxh + rbase * (long)DIP + DI + c;
    float* outp = g_xbc + (rbase + t0) * (long)CD + c;

    float in[CTT + 3];
    if (d == 0) {
#pragma unroll
        for (int j = 0; j < CTT + 3; j++) {
            int tt = t0 - 3 + j;
            in[j] = (tt >= 0) ? __half2float(zin[(long)tt * DIP]) : 0.f;
        }
#pragma unroll
        for (int i = 0; i < CTT; i++) {
            float a = bias;
            a = fmaf(w0, in[i], a); a = fmaf(w1, in[i+1], a);
            a = fmaf(w2, in[i+2], a); a = fmaf(w3, in[i+3], a);
            outp[(long)i * CD] = siluf(a);
        }
    } else {
#pragma unroll
        for (int j = 0; j < CTT + 3; j++) {
            int tt = t0 + j;
            in[j] = (tt < LL) ? __half2float(zin[(long)tt * DIP]) : 0.f;
        }
#pragma unroll
        for (int i = 0; i < CTT; i++) {
            float a = bias;
            a = fmaf(w3, in[i], a); a = fmaf(w2, in[i+1], a);
            a = fmaf(w1, in[i+2], a); a = fmaf(w0, in[i+3], a);
            outp[(long)i * CD] = siluf(a);
        }
    }
}

// ---------------- scan pass 1: chunk scans with FUSED x-conv+SiLU (64 thr) ----------------
__global__ __launch_bounds__(64)
void chunk_scan_k(const float* __restrict__ DpF, const float* __restrict__ DpB,
                  const float* __restrict__ cwF, const float* __restrict__ cbF,
                  const float* __restrict__ cwB, const float* __restrict__ cbB)
{
    int blk = blockIdx.x;
    int c   = blk & (NC - 1);
    int sid = blk >> 4;
    int d = sid >> 7, b = (sid >> 4) & 7, h = sid & 15;
    int p = threadIdx.x;

    __shared__ float  sBC[2][8][36];
    __shared__ __half sZ [2][11][64];
    float hs[16];
#pragma unroll
    for (int n = 0; n < 16; n++) hs[n] = 0.f;
    float dp = (d == 0 ? DpF : DpB)[h];
    long base0 = (long)d * MT + (long)b * LL;
    int s0 = c * CL;

    const int ch = h * HD + p;
    const float* wv = (d == 0 ? cwF : cwB) + ch * 4;
    const float w0 = wv[0], w1 = wv[1], w2 = wv[2], w3 = wv[3];
    const float cbias = (d == 0 ? cbF : cbB)[ch];

    auto rowof = [&](int s) -> long {
        int t = (d == 0) ? s : (LL - 1 - s);
        return base0 + t;
    };
    auto loadgrp = [&](int gg, int buf) {
        {
            int j = p >> 3, seg = p & 7;
            long row = rowof(s0 + gg * 8 + j);
            cpa16(&sBC[buf][j][seg * 4], &g_xbc[row * (long)CD + DI + seg * 4]);
        }
#pragma unroll
        for (int it = 0; it < 2; it++) {
            int idx2 = p + it * 64;
            if (idx2 < 88) {
                int j = idx2 >> 3, seg = idx2 & 7;
                int t = (d == 0) ? (s0 + gg * 8 - 3 + j)
                                 : (LL - 8 - s0 - gg * 8 + j);
                void* dst = (void*)&sZ[buf][j][seg * 8];
                if ((unsigned)t < (unsigned)LL)
                    cpa16(dst, &g_zxh[(base0 + t) * (long)DIP + DI + h * HD + seg * 8]);
                else
                    *(uint4*)dst = make_uint4(0, 0, 0, 0);
            }
        }
        if (p < 8) {
            long row = rowof(s0 + gg * 8 + p);
            cpa4(&sBC[buf][p][32], &g_dt[row * (long)NH + h]);
        } else if (p < 16) {
            long row = rowof(s0 + gg * 8 + (p - 8));
            cpa4(&sBC[buf][p - 8][33], &g_dA[row * (long)NH + h]);
        }
    };

    loadgrp(0, 0);
    CP_COMMIT();

    float P = 1.f;
    for (int gg = 0; gg < 16; gg++) {
        int buf = gg & 1;
        if (gg + 1 < 16) {
            loadgrp(gg + 1, buf ^ 1);
            CP_COMMIT();
            CP_WAIT(1);
        } else {
            CP_WAIT(0);
        }
        __syncthreads();
#pragma unroll
        for (int j = 0; j < 8; j++) {
            float a = cbias;
            if (d == 0) {
                a = fmaf(w0, __half2float(sZ[buf][j    ][p]), a);
                a = fmaf(w1, __half2float(sZ[buf][j + 1][p]), a);
                a = fmaf(w2, __half2float(sZ[buf][j + 2][p]), a);
                a = fmaf(w3, __half2float(sZ[buf][j + 3][p]), a);
            } else {
                a = fmaf(w3, __half2float(sZ[buf][7 - j ][p]), a);
                a = fmaf(w2, __half2float(sZ[buf][8 - j ][p]), a);
                a = fmaf(w1, __half2float(sZ[buf][9 - j ][p]), a);
                a = fmaf(w0, __half2float(sZ[buf][10 - j][p]), a);
            }
            float xv = siluf(a);

            float dtv = sBC[buf][j][32], dAv = sBC[buf][j][33];
            float coef = dtv * xv;
            float y = 0.f;
#pragma unroll
            for (int n = 0; n < 16; n += 2) {
                float2 Bn = *(const float2*)&sBC[buf][j][n];
                float2 Cn = *(const float2*)&sBC[buf][j][16 + n];
                hs[n]   = fmaf(hs[n],   dAv, coef * Bn.x);
                y       = fmaf(hs[n],   Cn.x, y);
                hs[n+1] = fmaf(hs[n+1], dAv, coef * Bn.y);
                y       = fmaf(hs[n+1], Cn.y, y);
            }
            P *= dAv;
            int s = s0 + gg * 8 + j;
            g_yh[rowof(s) * (long)DI + h * HD + p] = __float2half(fmaf(dp, xv, y));
            if (p == 0) g_P[(size_t)sid * LL + s] = P;
        }
        __syncthreads();
    }

    float* Sp = g_S + (size_t)blk * (HD * 16) + p * 16;
#pragma unroll
    for (int n = 0; n < 16; n++) Sp[n] = hs[n];
}

// ---------------- scan pass 2: chunk-state propagation, prefetched ----------------
__global__ __launch_bounds__(64)
void state_scan_k()
{
    int sid = blockIdx.x;
    int p = threadIdx.x;
    __shared__ float sP[16];
    if (p < 16) sP[p] = g_P[(size_t)sid * LL + p * CL + CL - 1];
    __syncthreads();

    size_t base = (size_t)sid * NC * (HD * 16) + p * 16;
    float hs[16], nxt[16];
#pragma unroll
    for (int n = 0; n < 16; n++) { hs[n] = 0.f; nxt[n] = g_S[base + n]; }

    for (int c = 0; c < NC; c++) {
        size_t off = base + (size_t)c * (HD * 16);
#pragma unroll
        for (int n = 0; n < 16; n++) g_hin[off + n] = hs[n];
        float cur[16];
#pragma unroll
        for (int n = 0; n < 16; n++) cur[n] = nxt[n];
        if (c + 1 < NC) {
            size_t off2 = off + HD * 16;
#pragma unroll
            for (int n = 0; n < 16; n++) nxt[n] = g_S[off2 + n];
        }
        float Pt = sP[c];
#pragma unroll
        for (int n = 0; n < 16; n++) hs[n] = fmaf(hs[n], Pt, cur[n]);
    }
}

// ---------------- scan pass 3: y[s] += P[s] * (C[s] . h_in)  (fp16 RMW) ----------------
__global__ __launch_bounds__(64)
void fixup_k()
{
    int blk = blockIdx.x;
    int cm  = blk % (NC - 1);
    int sid = blk / (NC - 1);
    int c   = cm + 1;
    int d = sid >> 7, b = (sid >> 4) & 7, h = sid & 15;
    int p = threadIdx.x;
    long base0 = (long)d * MT + (long)b * LL;

    size_t off = ((size_t)sid * NC + c) * (HD * 16) + p * 16;
    float hin[16];
#pragma unroll
    for (int n = 0; n < 16; n++) hin[n] = g_hin[off + n];

    __shared__ float sC[4][16];
    __shared__ float sP[4];
    int s0 = c * CL;

    for (int i = 0; i < CL; i += 4) {
        {
            int tsub = p >> 4, n = p & 15;
            int s = s0 + i + tsub;
            int t = (d == 0) ? s : (LL - 1 - s);
            sC[tsub][n] = g_xbc[(base0 + t) * (long)CD + DI + 16 + n];
            if (n == 0) sP[tsub] = g_P[(size_t)sid * LL + s];
        }
        __syncthreads();
        float av[4];
#pragma unroll
        for (int j = 0; j < 4; j++) {
            float y = 0.f;
#pragma unroll
            for (int n = 0; n < 16; n++) y = fmaf(hin[n], sC[j][n], y);
            av[j] = y;
        }
#pragma unroll
        for (int j = 0; j < 4; j++) {
            int s = s0 + i + j;
            int t = (d == 0) ? s : (LL - 1 - s);
            __half* yp = &g_yh[(base0 + t) * (long)DI + h * HD + p];
            *yp = __float2half(__half2float(*yp) + sP[j] * av[j]);
        }
        __syncthreads();
    }
}

// ---------------- gated RMSNorm: 2 tokens/block, 8 elems/thread, uint4 loads ----------------
__global__ __launch_bounds__(256)
void gnorm_k(const float* __restrict__ nwF, const float* __restrict__ nwB)
{
    long r  = (long)blockIdx.x * 2 + (threadIdx.x >> 7);
    int  tl = threadIdx.x & 127;
    int  sb = threadIdx.x >> 7;
    int  d  = (int)(r / MT);
    const float* nw = (d == 0) ? nwF : nwB;
    int i0 = tl * 8;

    __half2 yv[4], zv[4];
    *(uint4*)yv = *(const uint4*)&g_yh [r * (long)DI  + i0];
    *(uint4*)zv = *(const uint4*)&g_zxh[r * (long)DIP + i0];

    float v[8];
    float ss = 0.f;
#pragma unroll
    for (int j = 0; j < 4; j++) {
        float y0 = __low2float(yv[j]), y1 = __high2float(yv[j]);
        float z0 = __low2float(zv[j]), z1 = __high2float(zv[j]);
        v[2*j]   = y0 * siluf(z0);
        v[2*j+1] = y1 * siluf(z1);
        ss = fmaf(v[2*j], v[2*j], ss);
        ss = fmaf(v[2*j+1], v[2*j+1], ss);
    }
#pragma unroll
    for (int off = 16; off; off >>= 1) ss += __shfl_xor_sync(~0u, ss, off);
    __shared__ float ws[2][4];
    if ((tl & 31) == 0) ws[sb][tl >> 5] = ss;
    __syncthreads();
    float tot = ws[sb][0] + ws[sb][1] + ws[sb][2] + ws[sb][3];
    float scale = rsqrtf(tot * (1.f / 1024.f) + 1e-5f);

    __half2 o[4];
#pragma unroll
    for (int j = 0; j < 4; j++)
        o[j] = __floats2half2_rn(v[2*j]   * scale * nw[i0 + 2*j],
                                 v[2*j+1] * scale * nw[i0 + 2*j + 1]);
    *(uint4*)&g_gh[r * (long)DI + i0] = *(uint4*)o;
}

// ---------------- launch ----------------
extern "C" void kernel_launch(void* const* d_in, const int* in_sizes, int n_in,
                              void* d_out, int out_size)
{
    const float* x    = (const float*)d_in[0];
    const float* ipwF = (const float*)d_in[1];
    const float* cwF  = (const float*)d_in[2];
    const float* cbF  = (const float*)d_in[3];
    const float* dbF  = (const float*)d_in[4];
    const float* alF  = (const float*)d_in[5];
    const float* dpF  = (const float*)d_in[6];
    const float* nwF  = (const float*)d_in[7];
    const float* opF  = (const float*)d_in[8];
    const float* ipwB = (const float*)d_in[9];
    const float* cwB  = (const float*)d_in[10];
    const float* cbB  = (const float*)d_in[11];
    const float* dbB  = (const float*)d_in[12];
    const float* alB  = (const float*)d_in[13];
    const float* dpB  = (const float*)d_in[14];
    const float* nwB  = (const float*)d_in[15];
    const float* opB  = (const float*)d_in[16];
    float* out = (float*)d_out;

    __half *zxh_d, *xh_d, *wih_d, *woh_d, *gh_d;
    cudaGetSymbolAddress((void**)&zxh_d, g_zxh);
    cudaGetSymbolAddress((void**)&xh_d,  g_xh);
    cudaGetSymbolAddress((void**)&wih_d, g_wih);
    cudaGetSymbolAddress((void**)&woh_d, g_woh);
    cudaGetSymbolAddress((void**)&gh_d,  g_gh);

    cudaFuncSetAttribute((const void*)gemm_in,
                         cudaFuncAttributeMaxDynamicSharedMemorySize, GEMM_SMEM);
    cudaFuncSetAttribute((const void*)gemm_out,
                         cudaFuncAttributeMaxDynamicSharedMemorySize, GEMM_SMEM);

    // 0) fp32 -> fp16 conversions (one launch)
    {
        int total = N4_X + 2 * N4_WI + 2 * N4_WO;
        tohalf_all<<<(total + 255) / 256, 256>>>(
            (const float4*)x, (const float4*)ipwF, (const float4*)ipwB,
            (const float4*)opF, (const float4*)opB,
            (__half2*)xh_d, (__half2*)wih_d, (__half2*)woh_d);
    }

    // 1) in_proj both directions + fused dadt tail blocks (x = 17)
    gemm_in<<<dim3(18, 128, 2), 256, GEMM_SMEM>>>(
        xh_d, wih_d, wih_d + (size_t)DIP * DM, zxh_d,
        x, ipwF, ipwB, dbF, alF, dbB, alB);

    // 2) depthwise conv + silu for B/C channels only
    conv_bc_k<<<256, 256>>>(cwF, cbF, cwB, cbB);

    // 3) chunked selective scan (fused x-conv; fp16 y)
    chunk_scan_k<<<NSCAN * NC, 64>>>(dpF, dpB, cwF, cbF, cwB, cbB);
    state_scan_k<<<NSCAN, 64>>>();
    fixup_k<<<NSCAN * (NC - 1), 64>>>();

    // 4) gated RMSNorm (2 tokens/block, vectorized)
    gnorm_k<<<MT, 256>>>(nwF, nwB);

    // 5) out_proj: single fp16 GEMM, K-concat fwd+bwd
    gemm_out<<<dim3(4, 128), 256, GEMM_SMEM>>>(
        gh_d, gh_d + (size_t)MT * DI,
        woh_d, woh_d + (size_t)DM * DI, out);
}